// round 11
// baseline (speedup 1.0000x reference)
#include <cuda_runtime.h>
#include <math.h>

#define Bq 32
#define Sq 512
#define Eq 256
#define Hq 512
#define Lq 48
#define Mq (Bq*Sq)

// ---------------- scratch ----------------
__device__ __align__(16) float g_XW[2][Mq][2048];
__device__ __align__(16) float g_H[2][Bq][Sq + 1][Hq];
__device__ __align__(16) float g_C[2][Bq][Hq];
__device__ __align__(16) float g_E[Mq][Lq];
__device__ float g_vpart[Bq][8][Lq];

// ---------------- init: zero boundary h slots + c ----------------
__global__ void init_kernel() {
    int idx = blockIdx.x * blockDim.x + threadIdx.x;
    if (idx < Bq * Hq) {
        int b = idx / Hq, j = idx % Hq;
        g_H[0][b][0][j] = 0.f;
        g_H[1][b][Sq][j] = 0.f;
        g_C[0][b][j] = 0.f;
        g_C[1][b][j] = 0.f;
    }
}

// ---------------- K1: embed-gather + input projection ----------------
__global__ __launch_bounds__(256) void proj_kernel(
    const int* __restrict__ tokens, const float* __restrict__ embed,
    const float* __restrict__ w_ih_f, const float* __restrict__ b_f,
    const float* __restrict__ w_ih_b, const float* __restrict__ b_b)
{
    __shared__ float xs[32 * 64];
    __shared__ float ws[32 * 64];
    __shared__ int toks[64];
    int dir = blockIdx.z;
    const float* w = dir ? w_ih_b : w_ih_f;
    const float* bias = dir ? b_b : b_f;
    int m0 = blockIdx.x * 64, g0 = blockIdx.y * 64;
    int tid = threadIdx.x;
    if (tid < 64) toks[tid] = tokens[m0 + tid];
    int tx = tid & 15, ty = tid >> 4;
    float acc[4][4];
#pragma unroll
    for (int a = 0; a < 4; a++)
#pragma unroll
        for (int c = 0; c < 4; c++) acc[a][c] = 0.f;
    for (int kc = 0; kc < 8; kc++) {
        __syncthreads();
        for (int q = tid; q < 512; q += 256) {
            int ml = q >> 3, k4 = q & 7;
            float4 v = *(const float4*)&embed[toks[ml] * Eq + kc * 32 + k4 * 4];
            xs[(k4 * 4 + 0) * 64 + ml] = v.x; xs[(k4 * 4 + 1) * 64 + ml] = v.y;
            xs[(k4 * 4 + 2) * 64 + ml] = v.z; xs[(k4 * 4 + 3) * 64 + ml] = v.w;
            float4 wv = *(const float4*)&w[(g0 + ml) * Eq + kc * 32 + k4 * 4];
            ws[(k4 * 4 + 0) * 64 + ml] = wv.x; ws[(k4 * 4 + 1) * 64 + ml] = wv.y;
            ws[(k4 * 4 + 2) * 64 + ml] = wv.z; ws[(k4 * 4 + 3) * 64 + ml] = wv.w;
        }
        __syncthreads();
        const float4* xs4 = (const float4*)xs;
        const float4* ws4 = (const float4*)ws;
#pragma unroll 4
        for (int k = 0; k < 32; k++) {
            float4 xv = xs4[k * 16 + tx];
            float4 wv = ws4[k * 16 + ty];
            float xr[4] = {xv.x, xv.y, xv.z, xv.w};
            float wr[4] = {wv.x, wv.y, wv.z, wv.w};
#pragma unroll
            for (int a = 0; a < 4; a++)
#pragma unroll
                for (int c = 0; c < 4; c++)
                    acc[a][c] = fmaf(xr[a], wr[c], acc[a][c]);
        }
    }
#pragma unroll
    for (int a = 0; a < 4; a++) {
        int m = m0 + tx * 4 + a, g = g0 + ty * 4;
        float4 o;
        o.x = acc[a][0] + bias[g + 0]; o.y = acc[a][1] + bias[g + 1];
        o.z = acc[a][2] + bias[g + 2]; o.w = acc[a][3] + bias[g + 3];
        *(float4*)&g_XW[dir][m][g] = o;
    }
}

// ---------------- K2: one LSTM step, both dirs ----------------
// grid (64 j-tiles, 2 dirs) = 128 CTAs, 256 threads, 64 KB dyn smem.
// CTA: 8 hidden units x 4 gates (32 rows) x 32 batches, K=512.
// Thread tile: 2 gate-rows (register w streams) x 2 batches (LDS.64).
__global__ __launch_bounds__(256) void step_kernel(
    int t, const float* __restrict__ w_hh_f, const float* __restrict__ w_hh_b)
{
    extern __shared__ float sm[];
    float* hs = sm;  // [k][b], stride 32
    int dir = blockIdx.y;
    int j0 = blockIdx.x * 8;
    int s = dir ? (Sq - 1 - t) : t;
    int prev_slot = dir ? (s + 1) : s;
    int out_slot = dir ? s : (s + 1);
    const float* w = dir ? w_hh_b : w_hh_f;
    int tid = threadIdx.x;

    // epilogue prefetch
    int eb = tid & 31, ejl = tid >> 5;
    float xw[4];
#pragma unroll
    for (int g4 = 0; g4 < 4; g4++)
        xw[g4] = g_XW[dir][eb * Sq + s][g4 * Hq + j0 + ejl];
    float cprev = g_C[dir][eb][j0 + ejl];

    // stage h_prev transposed: [k][b] (batch-fast -> conflict-free STS)
    for (int q = tid; q < 4096; q += 256) {
        int k4 = q >> 5, b = q & 31;
        float4 v = *(const float4*)&g_H[dir][b][prev_slot][k4 * 4];
        hs[(k4 * 4 + 0) * 32 + b] = v.x;
        hs[(k4 * 4 + 1) * 32 + b] = v.y;
        hs[(k4 * 4 + 2) * 32 + b] = v.z;
        hs[(k4 * 4 + 3) * 32 + b] = v.w;
    }
    __syncthreads();

    int r2 = tid >> 4;            // 0..15 -> rows 2*r2, 2*r2+1 (same gate)
    int b2 = tid & 15;            // batches 2*b2, 2*b2+1
    int ra = 2 * r2;
    int growa = (ra >> 3) * Hq + j0 + (ra & 7);
    const float4* wa4 = (const float4*)&w[growa * Hq];
    const float4* wb4 = (const float4*)&w[(growa + 1) * Hq];
    const float2* hp2 = (const float2*)hs;  // hs[k*32 + 2*b2] -> hp2[k*16 + b2]
    float a00 = 0.f, a01 = 0.f, a10 = 0.f, a11 = 0.f;
#pragma unroll 4
    for (int k4 = 0; k4 < 128; k4++) {
        float4 wva = wa4[k4];
        float4 wvb = wb4[k4];
        float2 h0 = hp2[(k4 * 4 + 0) * 16 + b2];
        float2 h1 = hp2[(k4 * 4 + 1) * 16 + b2];
        float2 h2 = hp2[(k4 * 4 + 2) * 16 + b2];
        float2 h3 = hp2[(k4 * 4 + 3) * 16 + b2];
        a00 = fmaf(wva.x, h0.x, a00); a01 = fmaf(wva.x, h0.y, a01);
        a10 = fmaf(wvb.x, h0.x, a10); a11 = fmaf(wvb.x, h0.y, a11);
        a00 = fmaf(wva.y, h1.x, a00); a01 = fmaf(wva.y, h1.y, a01);
        a10 = fmaf(wvb.y, h1.x, a10); a11 = fmaf(wvb.y, h1.y, a11);
        a00 = fmaf(wva.z, h2.x, a00); a01 = fmaf(wva.z, h2.y, a01);
        a10 = fmaf(wvb.z, h2.x, a10); a11 = fmaf(wvb.z, h2.y, a11);
        a00 = fmaf(wva.w, h3.x, a00); a01 = fmaf(wva.w, h3.y, a01);
        a10 = fmaf(wvb.w, h3.x, a10); a11 = fmaf(wvb.w, h3.y, a11);
    }
    __syncthreads();
    float* gsum = sm;  // [r][b] 32x32 (overlays hs, protected by syncs)
    gsum[ra * 32 + 2 * b2 + 0] = a00;
    gsum[ra * 32 + 2 * b2 + 1] = a01;
    gsum[(ra + 1) * 32 + 2 * b2 + 0] = a10;
    gsum[(ra + 1) * 32 + 2 * b2 + 1] = a11;
    __syncthreads();

    float gi = gsum[(0 * 8 + ejl) * 32 + eb] + xw[0];
    float gf = gsum[(1 * 8 + ejl) * 32 + eb] + xw[1];
    float gg = gsum[(2 * 8 + ejl) * 32 + eb] + xw[2];
    float go = gsum[(3 * 8 + ejl) * 32 + eb] + xw[3];
    float ig = 1.f / (1.f + expf(-gi));
    float fg = 1.f / (1.f + expf(-gf));
    float og = 1.f / (1.f + expf(-go));
    float c = fg * cprev + ig * tanhf(gg);
    float h = og * tanhf(c);
    g_C[dir][eb][j0 + ejl] = c;
    g_H[dir][eb][out_slot][j0 + ejl] = h;
}

// ---------------- K3: emission logits -> e = exp ----------------
__global__ __launch_bounds__(256) void emis_kernel(
    const float* __restrict__ w_em, const float* __restrict__ b_em)
{
    extern __shared__ float hs[];  // [row][k] stride 1028 (odd*4: conflict-free)
    int m0 = blockIdx.x * 32;
    int tid = threadIdx.x;
    for (int q = tid; q < 8192; q += 256) {
        int row = q >> 8, k4 = q & 255;
        int m = m0 + row, b = m >> 9, sidx = m & 511;
        int k = k4 * 4;
        const float* src = (k < Hq) ? &g_H[0][b][sidx + 1][k]
                                    : &g_H[1][b][sidx][k - Hq];
        *(float4*)&hs[row * 1028 + k] = *(const float4*)src;
    }
    __syncthreads();
    int row = tid & 31, lg = tid >> 5;  // 8 groups x 6 labels
    float acc[6];
#pragma unroll
    for (int c = 0; c < 6; c++) acc[c] = 0.f;
    const float4* hr = (const float4*)&hs[row * 1028];
    for (int k4 = 0; k4 < 256; k4++) {
        float4 hv = hr[k4];
#pragma unroll
        for (int c = 0; c < 6; c++) {
            int l = lg * 6 + c;
            float4 wv = *(const float4*)&w_em[l * (2 * Hq) + k4 * 4];
            acc[c] = fmaf(hv.x, wv.x, acc[c]);
            acc[c] = fmaf(hv.y, wv.y, acc[c]);
            acc[c] = fmaf(hv.z, wv.z, acc[c]);
            acc[c] = fmaf(hv.w, wv.w, acc[c]);
        }
    }
    int m = m0 + row;
#pragma unroll
    for (int c = 0; c < 6; c++) {
        int l = lg * 6 + c;
        g_E[m][l] = expf(acc[c] + b_em[l]);
    }
}

// ---------------- K4: CRF partial sums (separable scan) ----------------
// alpha_i = e[b,0,i] + sum_{t=1}^{len-1} (m_t + log sum_j exp(exp(transition)_ij) * exp(e_tj - m_t))
__global__ __launch_bounds__(64) void vpart_kernel(
    const float* __restrict__ transition, const int* __restrict__ length)
{
    __shared__ float ET[Lq * Lq];   // exp(T) = exp(exp(transition))
    __shared__ float erow[Lq];
    __shared__ float wrow[Lq];
    int b = blockIdx.x, chunk = blockIdx.y;
    int tid = threadIdx.x;
    int len = length[b];
    for (int idx = tid; idx < Lq * Lq; idx += 64)
        ET[idx] = expf(expf(transition[idx]));
    float vacc = 0.f;
    int t0 = chunk * 64;
    for (int tt = 0; tt < 64; tt++) {
        int t = t0 + tt;
        if (t >= len) break;
        __syncthreads();
        if (t == 0) continue;
        if (tid < Lq) erow[tid] = g_E[b * Sq + t][tid];
        __syncthreads();
        float m = -1e30f;
        for (int j = 0; j < Lq; j++) m = fmaxf(m, erow[j]);
        if (tid < Lq) wrow[tid] = expf(erow[tid] - m);
        __syncthreads();
        if (tid < Lq) {
            float dot = 0.f;
            const float* et = &ET[tid * Lq];
            for (int j = 0; j < Lq; j++) dot = fmaf(et[j], wrow[j], dot);
            vacc += m + logf(dot);
        }
    }
    if (tid < Lq) g_vpart[b][chunk][tid] = vacc;
}

// ---------------- K5: finalize ----------------
__global__ __launch_bounds__(256) void final_kernel(
    const int* __restrict__ labels, const int* __restrict__ length,
    const float* __restrict__ transition, float* __restrict__ out)
{
    __shared__ float sal[Lq];
    __shared__ float red[256];
    int b = blockIdx.x, tid = threadIdx.x;
    int len = length[b];
    if (tid < Lq) {
        float a = g_E[b * Sq][tid];
        for (int c = 0; c < 8; c++) a += g_vpart[b][c][tid];
        sal[tid] = a;
    }
    const int* lab = &labels[b * Sq];
    float r = 0.f;
    for (int s = tid; s < Sq; s += 256) {
        if (s < len) {
            r += g_E[b * Sq + s][lab[s]];
            if (s >= 1) r += expf(transition[lab[s - 1] * Lq + lab[s]]);
        }
    }
    red[tid] = r;
    __syncthreads();
    for (int off = 128; off > 0; off >>= 1) {
        if (tid < off) red[tid] += red[tid + off];
        __syncthreads();
    }
    if (tid == 0) {
        float m = -1e30f;
        for (int j = 0; j < Lq; j++) m = fmaxf(m, sal[j]);
        float ss = 0.f;
        for (int j = 0; j < Lq; j++) ss += expf(sal[j] - m);
        out[b] = m + logf(ss) - red[0];
    }
}

extern "C" void kernel_launch(void* const* d_in, const int* in_sizes, int n_in,
                              void* d_out, int out_size)
{
    const int*   tokens     = (const int*)d_in[0];
    const int*   length     = (const int*)d_in[1];
    const int*   labels     = (const int*)d_in[2];
    const float* embed      = (const float*)d_in[3];
    const float* w_ih_f     = (const float*)d_in[4];
    const float* w_hh_f     = (const float*)d_in[5];
    const float* b_f        = (const float*)d_in[6];
    const float* w_ih_b     = (const float*)d_in[7];
    const float* w_hh_b     = (const float*)d_in[8];
    const float* b_b        = (const float*)d_in[9];
    const float* w_em       = (const float*)d_in[10];
    const float* b_em       = (const float*)d_in[11];
    const float* transition = (const float*)d_in[12];
    float* out = (float*)d_out;

    static bool attr_done = false;
    if (!attr_done) {
        cudaFuncSetAttribute(step_kernel,
            cudaFuncAttributeMaxDynamicSharedMemorySize, 512 * 32 * 4);
        cudaFuncSetAttribute(emis_kernel,
            cudaFuncAttributeMaxDynamicSharedMemorySize, 32 * 1028 * 4);
        attr_done = true;
    }

    init_kernel<<<64, 256>>>();
    proj_kernel<<<dim3(256, 32, 2), 256>>>(tokens, embed, w_ih_f, b_f, w_ih_b, b_b);
    for (int t = 0; t < Sq; t++)
        step_kernel<<<dim3(64, 2), 256, 512 * 32 * 4>>>(t, w_hh_f, w_hh_b);
    emis_kernel<<<512, 256, 32 * 1028 * 4>>>(w_em, b_em);
    vpart_kernel<<<dim3(32, 8), 64>>>(transition, length);
    final_kernel<<<32, 256>>>(labels, length, transition, out);
}

// round 13
// speedup vs baseline: 2.1426x; 2.1426x over previous
#include <cuda_runtime.h>
#include <math.h>

#define Bq 32
#define Sq 512
#define Eq 256
#define Hq 512
#define Lq 48
#define Mq (Bq*Sq)

// ---------------- scratch ----------------
__device__ __align__(16) float g_XW[2][Mq][2048];
__device__ __align__(16) float g_H[2][Bq][Sq + 1][Hq];      // for emission
__device__ __align__(16) float g_Ht[2][Sq + 1][Hq][Bq];     // transposed, for recurrence staging
__device__ __align__(16) float g_E[Mq][Lq];
__device__ float g_vpart[Bq][8][Lq];
__device__ unsigned g_bar;

// ---------------- init: zero boundary h slots (transposed buf) + barrier ----------------
__global__ void init_kernel() {
    int idx = blockIdx.x * blockDim.x + threadIdx.x;   // 0..16383
    ((float*)g_Ht[0][0])[idx]  = 0.f;
    ((float*)g_Ht[1][Sq])[idx] = 0.f;
    if (idx == 0) g_bar = 0u;
}

// ---------------- K1: embed-gather + input projection ----------------
__global__ __launch_bounds__(256) void proj_kernel(
    const int* __restrict__ tokens, const float* __restrict__ embed,
    const float* __restrict__ w_ih_f, const float* __restrict__ b_f,
    const float* __restrict__ w_ih_b, const float* __restrict__ b_b)
{
    __shared__ float xs[32 * 64];
    __shared__ float ws[32 * 64];
    __shared__ int toks[64];
    int dir = blockIdx.z;
    const float* w = dir ? w_ih_b : w_ih_f;
    const float* bias = dir ? b_b : b_f;
    int m0 = blockIdx.x * 64, g0 = blockIdx.y * 64;
    int tid = threadIdx.x;
    if (tid < 64) toks[tid] = tokens[m0 + tid];
    int tx = tid & 15, ty = tid >> 4;
    float acc[4][4];
#pragma unroll
    for (int a = 0; a < 4; a++)
#pragma unroll
        for (int c = 0; c < 4; c++) acc[a][c] = 0.f;
    for (int kc = 0; kc < 8; kc++) {
        __syncthreads();
        for (int q = tid; q < 512; q += 256) {
            int ml = q >> 3, k4 = q & 7;
            float4 v = *(const float4*)&embed[toks[ml] * Eq + kc * 32 + k4 * 4];
            xs[(k4 * 4 + 0) * 64 + ml] = v.x; xs[(k4 * 4 + 1) * 64 + ml] = v.y;
            xs[(k4 * 4 + 2) * 64 + ml] = v.z; xs[(k4 * 4 + 3) * 64 + ml] = v.w;
            float4 wv = *(const float4*)&w[(g0 + ml) * Eq + kc * 32 + k4 * 4];
            ws[(k4 * 4 + 0) * 64 + ml] = wv.x; ws[(k4 * 4 + 1) * 64 + ml] = wv.y;
            ws[(k4 * 4 + 2) * 64 + ml] = wv.z; ws[(k4 * 4 + 3) * 64 + ml] = wv.w;
        }
        __syncthreads();
        const float4* xs4 = (const float4*)xs;
        const float4* ws4 = (const float4*)ws;
#pragma unroll 4
        for (int k = 0; k < 32; k++) {
            float4 xv = xs4[k * 16 + tx];
            float4 wv = ws4[k * 16 + ty];
            float xr[4] = {xv.x, xv.y, xv.z, xv.w};
            float wr[4] = {wv.x, wv.y, wv.z, wv.w};
#pragma unroll
            for (int a = 0; a < 4; a++)
#pragma unroll
                for (int c = 0; c < 4; c++)
                    acc[a][c] = fmaf(xr[a], wr[c], acc[a][c]);
        }
    }
#pragma unroll
    for (int a = 0; a < 4; a++) {
        int m = m0 + tx * 4 + a, g = g0 + ty * 4;
        float4 o;
        o.x = acc[a][0] + bias[g + 0]; o.y = acc[a][1] + bias[g + 1];
        o.z = acc[a][2] + bias[g + 2]; o.w = acc[a][3] + bias[g + 3];
        *(float4*)&g_XW[dir][m][g] = o;
    }
}

// ---------------- K2: persistent bi-LSTM recurrence ----------------
// 128 CTAs (64 j-tiles x 2 dirs) = single wave, 256 threads, 131584 B smem.
// W_hh slice resident in smem across all 512 steps; grid barrier per step.
#define WST 516   // smem row stride for W (bank-skewed)
__global__ __launch_bounds__(256) void lstm_persist(
    const float* __restrict__ w_hh_f, const float* __restrict__ w_hh_b)
{
    extern __shared__ float sm[];
    float* hs = sm;              // [k][b] stride 32, 16384 floats
    float* ws = sm + 16384;      // 32 rows x WST
    int cid = blockIdx.x;
    int dir = cid >> 6;
    int j0 = (cid & 63) * 8;
    const float* w = dir ? w_hh_b : w_hh_f;
    int tid = threadIdx.x;

    // load W slice once: rows r=0..31 -> gate r>>3, unit j0+(r&7)
    for (int q = tid; q < 4096; q += 256) {
        int row = q >> 7, k4 = q & 127;
        int grow = (row >> 3) * Hq + j0 + (row & 7);
        *(float4*)&ws[row * WST + k4 * 4] =
            *(const float4*)&w[grow * Hq + k4 * 4];
    }

    int eb = tid & 31, ejl = tid >> 5;        // epilogue: batch, local j
    int r2 = tid >> 4, b2 = tid & 15;         // compute: row-pair, batch-pair
    int ra = 2 * r2;
    const float4* wa4 = (const float4*)&ws[ra * WST];
    const float4* wb4 = (const float4*)&ws[(ra + 1) * WST];
    const float2* hp2 = (const float2*)hs;
    float* gsum = sm;                         // overlays hs (sync-protected)
    float cprev = 0.f;

    for (int t = 0; t < Sq; t++) {
        int s = dir ? (Sq - 1 - t) : t;
        int prev_slot = dir ? (s + 1) : s;
        int out_slot = dir ? s : (s + 1);

        // prefetch xw for epilogue
        float xw0 = g_XW[dir][eb * Sq + s][0 * Hq + j0 + ejl];
        float xw1 = g_XW[dir][eb * Sq + s][1 * Hq + j0 + ejl];
        float xw2 = g_XW[dir][eb * Sq + s][2 * Hq + j0 + ejl];
        float xw3 = g_XW[dir][eb * Sq + s][3 * Hq + j0 + ejl];

        // stage h_prev: contiguous 64 KB, already [k][b]
        {
            const float4* src = (const float4*)&g_Ht[dir][prev_slot][0][0];
            float4* dst = (float4*)hs;
#pragma unroll
            for (int i = 0; i < 16; i++)
                dst[tid + i * 256] = src[tid + i * 256];
        }
        __syncthreads();

        float a00 = 0.f, a01 = 0.f, a10 = 0.f, a11 = 0.f;
#pragma unroll 4
        for (int k4 = 0; k4 < 128; k4++) {
            float4 wva = wa4[k4];
            float4 wvb = wb4[k4];
            float2 h0 = hp2[(k4 * 4 + 0) * 16 + b2];
            float2 h1 = hp2[(k4 * 4 + 1) * 16 + b2];
            float2 h2 = hp2[(k4 * 4 + 2) * 16 + b2];
            float2 h3 = hp2[(k4 * 4 + 3) * 16 + b2];
            a00 = fmaf(wva.x, h0.x, a00); a01 = fmaf(wva.x, h0.y, a01);
            a10 = fmaf(wvb.x, h0.x, a10); a11 = fmaf(wvb.x, h0.y, a11);
            a00 = fmaf(wva.y, h1.x, a00); a01 = fmaf(wva.y, h1.y, a01);
            a10 = fmaf(wvb.y, h1.x, a10); a11 = fmaf(wvb.y, h1.y, a11);
            a00 = fmaf(wva.z, h2.x, a00); a01 = fmaf(wva.z, h2.y, a01);
            a10 = fmaf(wvb.z, h2.x, a10); a11 = fmaf(wvb.z, h2.y, a11);
            a00 = fmaf(wva.w, h3.x, a00); a01 = fmaf(wva.w, h3.y, a01);
            a10 = fmaf(wvb.w, h3.x, a10); a11 = fmaf(wvb.w, h3.y, a11);
        }
        __syncthreads();
        gsum[ra * 32 + 2 * b2 + 0] = a00;
        gsum[ra * 32 + 2 * b2 + 1] = a01;
        gsum[(ra + 1) * 32 + 2 * b2 + 0] = a10;
        gsum[(ra + 1) * 32 + 2 * b2 + 1] = a11;
        __syncthreads();

        float gi = gsum[(0 * 8 + ejl) * 32 + eb] + xw0;
        float gf = gsum[(1 * 8 + ejl) * 32 + eb] + xw1;
        float gg = gsum[(2 * 8 + ejl) * 32 + eb] + xw2;
        float go = gsum[(3 * 8 + ejl) * 32 + eb] + xw3;
        float ig = 1.f / (1.f + expf(-gi));
        float fg = 1.f / (1.f + expf(-gf));
        float og = 1.f / (1.f + expf(-go));
        float c = fg * cprev + ig * tanhf(gg);
        float h = og * tanhf(c);
        cprev = c;
        g_H[dir][eb][out_slot][j0 + ejl] = h;          // for emission
        g_Ht[dir][out_slot][j0 + ejl][eb] = h;         // coalesced, for next step

        // grid barrier (monotonic counter, reset by init each launch)
        __threadfence();
        __syncthreads();
        if (tid == 0) {
            atomicAdd(&g_bar, 1u);
            unsigned target = (unsigned)(t + 1) * 128u;
            while (*(volatile unsigned*)&g_bar < target) {}
        }
        __syncthreads();
    }
}

// ---------------- K3: emission logits -> e = exp ----------------
__global__ __launch_bounds__(256) void emis_kernel(
    const float* __restrict__ w_em, const float* __restrict__ b_em)
{
    extern __shared__ float hs[];  // [row][k] stride 1028
    int m0 = blockIdx.x * 32;
    int tid = threadIdx.x;
    for (int q = tid; q < 8192; q += 256) {
        int row = q >> 8, k4 = q & 255;
        int m = m0 + row, b = m >> 9, sidx = m & 511;
        int k = k4 * 4;
        const float* src = (k < Hq) ? &g_H[0][b][sidx + 1][k]
                                    : &g_H[1][b][sidx][k - Hq];
        *(float4*)&hs[row * 1028 + k] = *(const float4*)src;
    }
    __syncthreads();
    int row = tid & 31, lg = tid >> 5;
    float acc[6];
#pragma unroll
    for (int c = 0; c < 6; c++) acc[c] = 0.f;
    const float4* hr = (const float4*)&hs[row * 1028];
    for (int k4 = 0; k4 < 256; k4++) {
        float4 hv = hr[k4];
#pragma unroll
        for (int c = 0; c < 6; c++) {
            int l = lg * 6 + c;
            float4 wv = *(const float4*)&w_em[l * (2 * Hq) + k4 * 4];
            acc[c] = fmaf(hv.x, wv.x, acc[c]);
            acc[c] = fmaf(hv.y, wv.y, acc[c]);
            acc[c] = fmaf(hv.z, wv.z, acc[c]);
            acc[c] = fmaf(hv.w, wv.w, acc[c]);
        }
    }
    int m = m0 + row;
#pragma unroll
    for (int c = 0; c < 6; c++) {
        int l = lg * 6 + c;
        g_E[m][l] = expf(acc[c] + b_em[l]);
    }
}

// ---------------- K4: CRF partial sums (separable scan) ----------------
__global__ __launch_bounds__(64) void vpart_kernel(
    const float* __restrict__ transition, const int* __restrict__ length)
{
    __shared__ float ET[Lq * Lq];   // exp(exp(transition))
    __shared__ float erow[Lq];
    __shared__ float wrow[Lq];
    int b = blockIdx.x, chunk = blockIdx.y;
    int tid = threadIdx.x;
    int len = length[b];
    for (int idx = tid; idx < Lq * Lq; idx += 64)
        ET[idx] = expf(expf(transition[idx]));
    float vacc = 0.f;
    int t0 = chunk * 64;
    for (int tt = 0; tt < 64; tt++) {
        int t = t0 + tt;
        if (t >= len) break;
        __syncthreads();
        if (t == 0) continue;
        if (tid < Lq) erow[tid] = g_E[b * Sq + t][tid];
        __syncthreads();
        float m = -1e30f;
        for (int j = 0; j < Lq; j++) m = fmaxf(m, erow[j]);
        if (tid < Lq) wrow[tid] = expf(erow[tid] - m);
        __syncthreads();
        if (tid < Lq) {
            float dot = 0.f;
            const float* et = &ET[tid * Lq];
            for (int j = 0; j < Lq; j++) dot = fmaf(et[j], wrow[j], dot);
            vacc += m + logf(dot);
        }
    }
    if (tid < Lq) g_vpart[b][chunk][tid] = vacc;
}

// ---------------- K5: finalize ----------------
__global__ __launch_bounds__(256) void final_kernel(
    const int* __restrict__ labels, const int* __restrict__ length,
    const float* __restrict__ transition, float* __restrict__ out)
{
    __shared__ float sal[Lq];
    __shared__ float red[256];
    int b = blockIdx.x, tid = threadIdx.x;
    int len = length[b];
    if (tid < Lq) {
        float a = g_E[b * Sq][tid];
        for (int c = 0; c < 8; c++) a += g_vpart[b][c][tid];
        sal[tid] = a;
    }
    const int* lab = &labels[b * Sq];
    float r = 0.f;
    for (int s = tid; s < Sq; s += 256) {
        if (s < len) {
            r += g_E[b * Sq + s][lab[s]];
            if (s >= 1) r += expf(transition[lab[s - 1] * Lq + lab[s]]);
        }
    }
    red[tid] = r;
    __syncthreads();
    for (int off = 128; off > 0; off >>= 1) {
        if (tid < off) red[tid] += red[tid + off];
        __syncthreads();
    }
    if (tid == 0) {
        float m = -1e30f;
        for (int j = 0; j < Lq; j++) m = fmaxf(m, sal[j]);
        float ss = 0.f;
        for (int j = 0; j < Lq; j++) ss += expf(sal[j] - m);
        out[b] = m + logf(ss) - red[0];
    }
}

extern "C" void kernel_launch(void* const* d_in, const int* in_sizes, int n_in,
                              void* d_out, int out_size)
{
    const int*   tokens     = (const int*)d_in[0];
    const int*   length     = (const int*)d_in[1];
    const int*   labels     = (const int*)d_in[2];
    const float* embed      = (const float*)d_in[3];
    const float* w_ih_f     = (const float*)d_in[4];
    const float* w_hh_f     = (const float*)d_in[5];
    const float* b_f        = (const float*)d_in[6];
    const float* w_ih_b     = (const float*)d_in[7];
    const float* w_hh_b     = (const float*)d_in[8];
    const float* b_b        = (const float*)d_in[9];
    const float* w_em       = (const float*)d_in[10];
    const float* b_em       = (const float*)d_in[11];
    const float* transition = (const float*)d_in[12];
    float* out = (float*)d_out;

    const int persist_smem = (16384 + 32 * WST) * 4;   // 131584 B
    static bool attr_done = false;
    if (!attr_done) {
        cudaFuncSetAttribute(lstm_persist,
            cudaFuncAttributeMaxDynamicSharedMemorySize, persist_smem);
        cudaFuncSetAttribute(emis_kernel,
            cudaFuncAttributeMaxDynamicSharedMemorySize, 32 * 1028 * 4);
        attr_done = true;
    }

    init_kernel<<<64, 256>>>();
    proj_kernel<<<dim3(256, 32, 2), 256>>>(tokens, embed, w_ih_f, b_f, w_ih_b, b_b);
    lstm_persist<<<128, 256, persist_smem>>>(w_hh_f, w_hh_b);
    emis_kernel<<<512, 256, 32 * 1028 * 4>>>(w_em, b_em);
    vpart_kernel<<<dim3(32, 8), 64>>>(transition, length);
    final_kernel<<<32, 256>>>(labels, length, transition, out);
}